// round 15
// baseline (speedup 1.0000x reference)
#include <cuda_runtime.h>
#include <math.h>
#include <stdint.h>

#define B 4
#define T 64
#define F 64
#define U 64
#define M 64
#define TF (T*F)
#define CPB 8          // CTAs per cluster (one cluster per batch)
#define RPC 8          // rows per CTA = T/CPB
#define WPR 4          // warps per row = 32/RPC
#define CHK 16         // reduction chunk = 64/WPR
#define NTH 1024

// exact incoming byte counts per phase mbarrier
#define BYTES_A (CPB*RPC*4 + CPB*F*8)   // idx_t + candidates = 256 + 4096
#define BYTES_B (CPB*M*4)               // logit partials     = 2048

// Accurate tanh for value paths (h, ms): abs err ~1e-7.
__device__ __forceinline__ float fast_tanh(float x) {
    float e = __expf(2.0f * x);
    return 1.0f - __fdividef(2.0f, e + 1.0f);
}
// Single-MUFU f32 tanh for the argmax-only score path (proven argmax-safe).
__device__ __forceinline__ float tanh_mufu(float x) {
    float y; asm("tanh.approx.f32 %0, %1;" : "=f"(y) : "f"(x)); return y;
}
__device__ __forceinline__ uint32_t smem_u32(const void* p) {
    uint32_t a;
    asm("{ .reg .u64 t; cvta.to.shared.u64 t, %1; cvt.u32.u64 %0, t; }" : "=r"(a) : "l"(p));
    return a;
}
// st.async remote-smem stores with mbarrier tx-completion
__device__ __forceinline__ void sta_b32(uint32_t dst, uint32_t mbar, int rank, uint32_t v) {
    uint32_t rd, rm;
    asm volatile("mapa.shared::cluster.u32 %0, %1, %2;" : "=r"(rd) : "r"(dst), "r"(rank));
    asm volatile("mapa.shared::cluster.u32 %0, %1, %2;" : "=r"(rm) : "r"(mbar), "r"(rank));
    asm volatile("st.async.shared::cluster.mbarrier::complete_tx::bytes.b32 [%0], %1, [%2];"
                 :: "r"(rd), "r"(v), "r"(rm) : "memory");
}
__device__ __forceinline__ void sta_b64(uint32_t dst, uint32_t mbar, int rank, unsigned long long v) {
    uint32_t rd, rm;
    asm volatile("mapa.shared::cluster.u32 %0, %1, %2;" : "=r"(rd) : "r"(dst), "r"(rank));
    asm volatile("mapa.shared::cluster.u32 %0, %1, %2;" : "=r"(rm) : "r"(mbar), "r"(rank));
    asm volatile("st.async.shared::cluster.mbarrier::complete_tx::bytes.b64 [%0], %1, [%2];"
                 :: "r"(rd), "l"(v), "r"(rm) : "memory");
}
#define MBAR_WAIT(mbar, par) do {                                                   \
    asm volatile("{\n\t.reg .pred P;\n"                                             \
        "W%=: mbarrier.try_wait.parity.acquire.cluster.shared::cta.b64 P, [%0], %1;\n\t" \
        "@P bra D%=;\n\t"                                                           \
        "bra W%=;\n"                                                                \
        "D%=:\n\t}" :: "r"(mbar), "r"(par) : "memory");                             \
} while (0)

__device__ __forceinline__ void cluster_arrive() {
    asm volatile("barrier.cluster.arrive.aligned;" ::: "memory");
}
__device__ __forceinline__ void cluster_wait() {
    asm volatile("barrier.cluster.wait.aligned;" ::: "memory");
}

// =====================================================================
// Cluster of 8 CTAs per batch, 32 warps per CTA. Row tl owned by a
// warp-quad splitting each 64-deep reduction into 16-iter chains.
// Cross-CTA sync: st.async + tx-mbarriers (no full cluster barriers on
// the critical path; the one init barrier is hidden behind phase 1).
// =====================================================================
__global__ void __launch_bounds__(NTH) __cluster_dims__(CPB, 1, 1)
fused_all(const float* __restrict__ inp,
          const float* __restrict__ Wk,
          const float* __restrict__ bk,
          const float* __restrict__ Wv,
          const float* __restrict__ bv,
          const float* __restrict__ w_s,
          const float* __restrict__ mem_keys,
          const float* __restrict__ mem_vals,
          float* __restrict__ d_out) {
    const int b    = blockIdx.x / CPB;
    const int r    = blockIdx.x % CPB;
    const int tid  = threadIdx.x;
    const int w    = tid >> 5;
    const int lane = tid & 31;
    const int tl   = w >> 2;         // row owned by this warp quad
    const int sub  = w & 3;          // quarter of the reduction dim

    __shared__ __align__(16) float s_in[RPC][F];
    __shared__ float s_hp[WPR][RPC][U];
    __shared__ float s_h [RPC][U];
    __shared__ float s_op[WPR][RPC][F];
    __shared__ float s_o [RPC][F];
    __shared__ float s_scp[WPR][RPC][F];
    __shared__ __align__(16) float s_ms[RPC*F];
    __shared__ unsigned long long s_candloc[F];
    __shared__ unsigned long long s_cand[CPB][F];
    __shared__ int   s_idxt[T];
    __shared__ float s_lp[CPB][M];
    __shared__ float s_ws[F];
    __shared__ float s_attn[M];
    __shared__ float s_tpart[16][F];
    __shared__ float s_amax[RPC], s_amin[RPC];
    __shared__ float s_wmm[2];
    __shared__ float s_imp;
    __shared__ __align__(8) unsigned long long s_mbar[2];   // [0]=A, [1]=B

    const uint32_t mbarA = smem_u32(&s_mbar[0]);
    const uint32_t mbarB = smem_u32(&s_mbar[1]);

    // init tx-mbarriers, then arrive+expect the full phase payloads
    if (tid == 0) {
        asm volatile("mbarrier.init.shared.b64 [%0], %1;" :: "r"(mbarA), "r"(1) : "memory");
        asm volatile("mbarrier.init.shared.b64 [%0], %1;" :: "r"(mbarB), "r"(1) : "memory");
        asm volatile("mbarrier.arrive.expect_tx.shared.b64 _, [%0], %1;"
                     :: "r"(mbarA), "r"(BYTES_A) : "memory");
        asm volatile("mbarrier.arrive.expect_tx.shared.b64 _, [%0], %1;"
                     :: "r"(mbarB), "r"(BYTES_B) : "memory");
    }
    __syncthreads();
    cluster_arrive();            // init visibility; wait deferred past phase 1

    if (tid < F) s_ws[tid] = w_s[tid];
    const float wlast = __ldg(w_s + 63);

    // ---- stage inputs ----
    if (tid < RPC*F)
        s_in[tid >> 6][tid & 63] = inp[(b*T + r*RPC)*F + tid];
    __syncthreads();

    // ---- h partials: quad splits f; u0 = 2*lane ----
    {
        const int fbase = sub*CHK;
        const int u0 = 2*lane;
        float a0 = 0.f, a1 = 0.f;
        #pragma unroll
        for (int f = 0; f < CHK; ++f) {
            float2 kk = *(const float2*)(Wk + (fbase + f)*U + u0);
            float x = s_in[tl][fbase + f];
            a0 = fmaf(x, kk.x, a0);
            a1 = fmaf(x, kk.y, a1);
        }
        s_hp[sub][tl][u0] = a0; s_hp[sub][tl][u0+1] = a1;
    }
    __syncthreads();
    if (tid < RPC*U) {
        const int t = tid >> 6, u = tid & 63;
        float s = __ldg(bk + u);
        #pragma unroll
        for (int q = 0; q < WPR; ++q) s += s_hp[q][t][u];
        s_h[t][u] = fast_tanh(s);
    }
    __syncthreads();

    // ---- output partials: quad splits u; f0 = 2*lane ----
    {
        const int ubase = sub*CHK;
        const int f0 = 2*lane;
        float o0 = 0.f, o1 = 0.f;
        #pragma unroll
        for (int u = 0; u < CHK; ++u) {
            float2 vv = *(const float2*)(Wv + (ubase + u)*F + f0);
            float hv = s_h[tl][ubase + u];
            o0 = fmaf(hv, vv.x, o0);
            o1 = fmaf(hv, vv.y, o1);
        }
        s_op[sub][tl][f0] = o0; s_op[sub][tl][f0+1] = o1;
    }
    __syncthreads();
    if (tid < RPC*F) {
        const int t = tid >> 6, f = tid & 63;
        float o = __ldg(bv + f);
        #pragma unroll
        for (int q = 0; q < WPR; ++q) o += s_op[q][t][f];
        s_o[t][f] = o;
        d_out[2*B*T + (b*T + r*RPC)*F + tid] = o;
    }
    __syncthreads();

    // ---- score partials: quad splits u; f0 = 2*lane ----
    {
        const int ubase = sub*CHK;
        const int f0 = 2*lane;
        const float c0 = s_o[tl][f0] * wlast, c1 = s_o[tl][f0+1] * wlast;
        float sc0 = 0.f, sc1 = 0.f;
        #pragma unroll
        for (int u = 0; u < CHK; ++u) {
            float hv = s_h[tl][ubase + u];
            sc0 += tanh_mufu(hv * c0);
            sc1 += tanh_mufu(hv * c1);
        }
        s_scp[sub][tl][f0] = sc0; s_scp[sub][tl][f0+1] = sc1;
    }
    __syncthreads();
    cluster_wait();   // all CTAs' mbarriers initialized (hidden by phase 1)

    // ---- idx_t (warps 0..7, row = w): fused partial-sum + argmax ----
    if (w < RPC) {
        const int f0 = 2*lane;
        float sc0 = 0.f, sc1 = 0.f;
        #pragma unroll
        for (int q = 0; q < WPR; ++q) {
            sc0 += s_scp[q][w][f0];
            sc1 += s_scp[q][w][f0+1];
        }
        float bvv = sc0; int bf = f0;
        if (sc1 > bvv) { bvv = sc1; bf = f0 + 1; }
        #pragma unroll
        for (int o = 16; o; o >>= 1) {
            float ov = __shfl_xor_sync(0xffffffffu, bvv, o);
            int   of = __shfl_xor_sync(0xffffffffu, bf,  o);
            if (ov > bvv || (ov == bvv && of < bf)) { bvv = ov; bf = of; }
        }
        if (lane < CPB)
            sta_b32(smem_u32(&s_idxt[r*RPC + w]), mbarA, lane, (uint32_t)bf);
    }
    // ---- per-f column-max candidate (warps 8,9), same sum order ----
    else if (w < RPC + 2) {
        const int f = (w - RPC)*32 + lane;
        float best = -INFINITY; int bt = 0;
        #pragma unroll
        for (int t = 0; t < RPC; ++t) {
            float v = 0.f;
            #pragma unroll
            for (int q = 0; q < WPR; ++q) v += s_scp[q][t][f];
            if (v > best) { best = v; bt = t; }
        }
        s_candloc[f] =
            ((unsigned long long)__float_as_uint(best) << 32) | (unsigned)(r*RPC + bt);
    }
    __syncthreads();

    // ---- push candidates: 1 (f, rank) pair per thread (512 pushes) ----
    if (tid < F*CPB)
        sta_b64(smem_u32(&s_cand[r][tid & 63]), mbarA, tid >> 6, s_candloc[tid & 63]);

    MBAR_WAIT(mbarA, 0);   // all idx_t + candidates delivered

    // ---- wmax/wmin (warp 0) ----
    if (w == 0) {
        float wv[2];
        #pragma unroll
        for (int hh = 0; hh < 2; ++hh) {
            const int f = lane + hh*32;
            unsigned long long c = s_cand[0][f];
            float best = __uint_as_float((unsigned)(c >> 32));
            int   bt   = (int)(c & 0xffffffffu);
            #pragma unroll
            for (int rr = 1; rr < CPB; ++rr) {
                unsigned long long cc = s_cand[rr][f];
                float v = __uint_as_float((unsigned)(cc >> 32));
                if (v > best) { best = v; bt = (int)(cc & 0xffffffffu); }
            }
            wv[hh] = s_ws[bt];
        }
        float mx = fmaxf(wv[0], wv[1]), mn = fminf(wv[0], wv[1]);
        #pragma unroll
        for (int o = 16; o; o >>= 1) {
            mx = fmaxf(mx, __shfl_xor_sync(0xffffffffu, mx, o));
            mn = fminf(mn, __shfl_xor_sync(0xffffffffu, mn, o));
        }
        if (lane == 0) { s_wmm[0] = mx; s_wmm[1] = mn; }
    }
    // ---- amax/amin: warps 16..23, row = w-16 ----
    else if (w >= 16 && w < 16 + RPC) {
        const int t = w - 16;
        float v0 = s_h[t][s_idxt[lane]];
        float v1 = s_h[t][s_idxt[lane + 32]];
        float mx = fmaxf(v0, v1), mn = fminf(v0, v1);
        #pragma unroll
        for (int o = 16; o; o >>= 1) {
            mx = fmaxf(mx, __shfl_xor_sync(0xffffffffu, mx, o));
            mn = fminf(mn, __shfl_xor_sync(0xffffffffu, mn, o));
        }
        if (lane == 0) { s_amax[t] = mx; s_amin[t] = mn; }
    }
    __syncthreads();

    // ---- ms ----
    if (tid < RPC*F) {
        const int t = tid >> 6;
        const float c   = s_o[t][tid & 63];
        const float wmax = s_wmm[0], wmin = s_wmm[1];
        const float amx = s_amax[t], amn = s_amin[t];
        float m = fmaxf(fmaxf(amx*wmax*c, amx*wmin*c),
                        fmaxf(amn*wmax*c, amn*wmin*c));
        s_ms[tid] = fast_tanh(m);
    }
    __syncthreads();

    // ---- logit partials: 32 warps, 2 m each ----
    {
        const float4* __restrict__ ms4 = (const float4*)s_ms;
        #pragma unroll
        for (int k = 0; k < 2; ++k) {
            const int m = w*2 + k;
            const float4* __restrict__ key4 =
                (const float4*)(mem_keys + m*TF + r*(RPC*F));
            float p0 = 0.f, p1 = 0.f, p2 = 0.f, p3 = 0.f;
            #pragma unroll
            for (int c = 0; c < 4; ++c) {
                float4 kk = key4[c*32 + lane];
                float4 mm = ms4[c*32 + lane];
                p0 = fmaf(kk.x, mm.x, p0);
                p1 = fmaf(kk.y, mm.y, p1);
                p2 = fmaf(kk.z, mm.z, p2);
                p3 = fmaf(kk.w, mm.w, p3);
            }
            float acc = (p0 + p1) + (p2 + p3);
            #pragma unroll
            for (int o = 16; o; o >>= 1)
                acc += __shfl_xor_sync(0xffffffffu, acc, o);
            if (lane < CPB)
                sta_b32(smem_u32(&s_lp[r][m]), mbarB, lane, __float_as_uint(acc));
        }
    }

    // ---- prefetch mem_vals rows while logits fly ----
    float rv[4];
    {
        const int f = tid & 63, q = tid >> 6;
        #pragma unroll
        for (int k = 0; k < 4; ++k)
            rv[k] = __ldg(mem_vals + (q*4 + k)*F + f);
    }
    MBAR_WAIT(mbarB, 0);   // all logit partials delivered

    // ---- softmax / importance (single warp) ----
    if (w == 0) {
        float l0 = 0.f, l1 = 0.f;
        #pragma unroll
        for (int rr = 0; rr < CPB; ++rr) {
            l0 += s_lp[rr][lane];
            l1 += s_lp[rr][lane + 32];
        }
        float mx = fmaxf(l0, l1);
        #pragma unroll
        for (int o = 16; o; o >>= 1)
            mx = fmaxf(mx, __shfl_xor_sync(0xffffffffu, mx, o));
        float e0 = __expf(l0 - mx), e1 = __expf(l1 - mx);
        float s = e0 + e1;
        #pragma unroll
        for (int o = 16; o; o >>= 1)
            s += __shfl_xor_sync(0xffffffffu, s, o);
        float inv = 1.0f / s;
        s_attn[lane]      = e0 * inv;
        s_attn[lane + 32] = e1 * inv;
        if (lane == 0) s_imp = inv;   // max(attn) = exp(0)/sum
    }
    __syncthreads();

    // ---- targets partials: 1024 threads, 4 m each (prefetched) ----
    {
        const int f = tid & 63, q = tid >> 6;
        float acc = 0.f;
        #pragma unroll
        for (int k = 0; k < 4; ++k)
            acc = fmaf(s_attn[q*4 + k], rv[k], acc);
        s_tpart[q][f] = acc;
    }
    __syncthreads();

    // ---- dist + importances: warps 0..7, row = w ----
    if (w < RPC) {
        float tg0 = 0.f, tg1 = 0.f;
        #pragma unroll
        for (int q = 0; q < 16; ++q) {
            tg0 += s_tpart[q][lane];
            tg1 += s_tpart[q][lane + 32];
        }
        float d0 = s_in[w][lane]      - tg0;
        float d1 = s_in[w][lane + 32] - tg1;
        float a2 = d0*d0 + d1*d1;
        #pragma unroll
        for (int o = 16; o; o >>= 1)
            a2 += __shfl_xor_sync(0xffffffffu, a2, o);
        if (lane == 0) {
            float nrm = sqrtf(a2);
            float hs  = fminf(fmaxf(0.2f*nrm + 0.5f, 0.f), 1.f);
            d_out[b*T + r*RPC + w]       = 0.5f - hs;
            d_out[B*T + b*T + r*RPC + w] = s_imp;
        }
    }
}

// =====================================================================
extern "C" void kernel_launch(void* const* d_in, const int* in_sizes, int n_in,
                              void* d_out, int out_size) {
    const float* inp      = (const float*)d_in[0];
    const float* Wk       = (const float*)d_in[1];
    const float* bk       = (const float*)d_in[2];
    const float* Wv       = (const float*)d_in[3];
    const float* bv       = (const float*)d_in[4];
    const float* w_s      = (const float*)d_in[5];
    const float* mem_keys = (const float*)d_in[6];
    const float* mem_vals = (const float*)d_in[7];

    fused_all<<<B*CPB, NTH>>>(inp, Wk, bk, Wv, bv, w_s, mem_keys, mem_vals,
                              (float*)d_out);
}

// round 16
// speedup vs baseline: 1.0226x; 1.0226x over previous
#include <cuda_runtime.h>
#include <math.h>
#include <stdint.h>

#define B 4
#define T 64
#define F 64
#define U 64
#define M 64
#define TF (T*F)
#define CPB 8          // CTAs per cluster (one cluster per batch)
#define RPC 8          // rows per CTA
#define NTH 1024       // 32 warps

// GEMM decomposition: 2 row-groups x 16 weight-chunks of 4 columns
#define TG   2
#define RPW  4         // rows per warp (RPC/TG)
#define NCHK 16        // weight chunks (32/TG)
#define CW   4         // columns per chunk (64/NCHK)

// Accurate tanh for value paths (h, ms): abs err ~1e-7.
__device__ __forceinline__ float fast_tanh(float x) {
    float e = __expf(2.0f * x);
    return 1.0f - __fdividef(2.0f, e + 1.0f);
}
// Single-MUFU f32 tanh for the argmax-only score path (proven argmax-safe).
__device__ __forceinline__ float tanh_mufu(float x) {
    float y; asm("tanh.approx.f32 %0, %1;" : "=f"(y) : "f"(x)); return y;
}
__device__ __forceinline__ uint32_t smem_u32(const void* p) {
    uint32_t a;
    asm("{ .reg .u64 t; cvta.to.shared.u64 t, %1; cvt.u32.u64 %0, t; }" : "=r"(a) : "l"(p));
    return a;
}
__device__ __forceinline__ void stc_f32(uint32_t saddr, int rank, float v) {
    uint32_t rr;
    asm volatile("mapa.shared::cluster.u32 %0, %1, %2;" : "=r"(rr) : "r"(saddr), "r"(rank));
    asm volatile("st.shared::cluster.f32 [%0], %1;" :: "r"(rr), "f"(v) : "memory");
}
__device__ __forceinline__ void stc_s32(uint32_t saddr, int rank, int v) {
    uint32_t rr;
    asm volatile("mapa.shared::cluster.u32 %0, %1, %2;" : "=r"(rr) : "r"(saddr), "r"(rank));
    asm volatile("st.shared::cluster.u32 [%0], %1;" :: "r"(rr), "r"(v) : "memory");
}
__device__ __forceinline__ void stc_u64(uint32_t saddr, int rank, unsigned long long v) {
    uint32_t rr;
    asm volatile("mapa.shared::cluster.u32 %0, %1, %2;" : "=r"(rr) : "r"(saddr), "r"(rank));
    asm volatile("st.shared::cluster.u64 [%0], %1;" :: "r"(rr), "l"(v) : "memory");
}
__device__ __forceinline__ void cluster_arrive() {
    asm volatile("barrier.cluster.arrive.aligned;" ::: "memory");
}
__device__ __forceinline__ void cluster_wait() {
    asm volatile("barrier.cluster.wait.aligned;" ::: "memory");
}

// =====================================================================
// Cluster of 8 CTAs per batch, 32 warps per CTA.
// GEMMs: warp (tg, fc) reads a 4-column weight chunk ONCE and applies it
// to 4 rows -> weight L1 traffic drops 4x vs one-row-per-warp-group.
// 32KB union scratch holds (in time sequence) h partials, out partials,
// score partials, ms, target partials.
// =====================================================================
__global__ void __launch_bounds__(NTH) __cluster_dims__(CPB, 1, 1)
fused_all(const float* __restrict__ inp,
          const float* __restrict__ Wk,
          const float* __restrict__ bk,
          const float* __restrict__ Wv,
          const float* __restrict__ bv,
          const float* __restrict__ w_s,
          const float* __restrict__ mem_keys,
          const float* __restrict__ mem_vals,
          float* __restrict__ d_out) {
    const int b    = blockIdx.x / CPB;
    const int r    = blockIdx.x % CPB;
    const int tid  = threadIdx.x;
    const int w    = tid >> 5;       // 0..31
    const int lane = tid & 31;

    __shared__ __align__(16) float s_U[NCHK*RPC*U];   // 32KB union scratch
    __shared__ __align__(16) float s_in[RPC][F];
    __shared__ float s_h [RPC][U];
    __shared__ float s_o [RPC][F];
    __shared__ unsigned long long s_candloc[F];
    __shared__ unsigned long long s_cand[CPB][F];
    __shared__ int   s_idxt[T];
    __shared__ float s_lp[CPB][M];
    __shared__ float s_ws[F];
    __shared__ float s_attn[M];
    __shared__ float s_amax[RPC], s_amin[RPC];
    __shared__ float s_wmm[2];
    __shared__ float s_imp;

    if (tid < F) s_ws[tid] = w_s[tid];
    const float wlast = __ldg(w_s + 63);

    // ---- stage inputs ----
    if (tid < RPC*F)
        s_in[tid >> 6][tid & 63] = inp[(b*T + r*RPC)*F + tid];
    __syncthreads();

    // ---- h partials: warp (tg, fc); 4 rows x 4 f-chunk; u0 = 2*lane ----
    {
        const int tg = w >> 4;           // 0..1
        const int fc = w & 15;           // 0..15
        const int u0 = 2*lane;
        float a0[RPW], a1[RPW];
        #pragma unroll
        for (int q = 0; q < RPW; ++q) { a0[q] = 0.f; a1[q] = 0.f; }
        #pragma unroll
        for (int f = 0; f < CW; ++f) {
            float2 kk = *(const float2*)(Wk + (fc*CW + f)*U + u0);
            #pragma unroll
            for (int q = 0; q < RPW; ++q) {
                float x = s_in[tg*RPW + q][fc*CW + f];
                a0[q] = fmaf(x, kk.x, a0[q]);
                a1[q] = fmaf(x, kk.y, a1[q]);
            }
        }
        #pragma unroll
        for (int q = 0; q < RPW; ++q) {
            s_U[(fc*RPC + tg*RPW + q)*U + u0]     = a0[q];
            s_U[(fc*RPC + tg*RPW + q)*U + u0 + 1] = a1[q];
        }
    }
    __syncthreads();
    if (tid < RPC*U) {   // combine h
        const int t = tid >> 6, u = tid & 63;
        float s = __ldg(bk + u);
        #pragma unroll
        for (int c = 0; c < NCHK; ++c) s += s_U[(c*RPC + t)*U + u];
        s_h[t][u] = fast_tanh(s);
    }
    __syncthreads();

    // ---- output partials: warp (tg, uc); f0 = 2*lane ----
    {
        const int tg = w >> 4;
        const int uc = w & 15;
        const int f0 = 2*lane;
        float o0[RPW], o1[RPW];
        #pragma unroll
        for (int q = 0; q < RPW; ++q) { o0[q] = 0.f; o1[q] = 0.f; }
        #pragma unroll
        for (int u = 0; u < CW; ++u) {
            float2 vv = *(const float2*)(Wv + (uc*CW + u)*F + f0);
            #pragma unroll
            for (int q = 0; q < RPW; ++q) {
                float hv = s_h[tg*RPW + q][uc*CW + u];
                o0[q] = fmaf(hv, vv.x, o0[q]);
                o1[q] = fmaf(hv, vv.y, o1[q]);
            }
        }
        #pragma unroll
        for (int q = 0; q < RPW; ++q) {
            s_U[(uc*RPC + tg*RPW + q)*F + f0]     = o0[q];
            s_U[(uc*RPC + tg*RPW + q)*F + f0 + 1] = o1[q];
        }
    }
    __syncthreads();
    if (tid < RPC*F) {   // combine output
        const int t = tid >> 6, f = tid & 63;
        float o = __ldg(bv + f);
        #pragma unroll
        for (int c = 0; c < NCHK; ++c) o += s_U[(c*RPC + t)*F + f];
        s_o[t][f] = o;
        d_out[2*B*T + (b*T + r*RPC)*F + tid] = o;
    }
    __syncthreads();

    // ---- score partials: warp quad per row (MUFU-bound; smem-only) ----
    // scp(sub, t, f) = s_U[(sub*RPC + t)*F + f], sub = 0..3
    {
        const int tl  = w >> 2;
        const int sub = w & 3;
        const int ubase = sub*16;
        const int f0 = 2*lane;
        const float c0 = s_o[tl][f0] * wlast, c1 = s_o[tl][f0+1] * wlast;
        float sc0 = 0.f, sc1 = 0.f;
        #pragma unroll
        for (int u = 0; u < 16; ++u) {
            float hv = s_h[tl][ubase + u];
            sc0 += tanh_mufu(hv * c0);
            sc1 += tanh_mufu(hv * c1);
        }
        s_U[(sub*RPC + tl)*F + f0]     = sc0;
        s_U[(sub*RPC + tl)*F + f0 + 1] = sc1;
    }
    __syncthreads();

    // ---- idx_t (warps 0..7): fused partial-sum + argmax_f (first max) ----
    if (w < RPC) {
        const int f0 = 2*lane;
        float sc0 = 0.f, sc1 = 0.f;
        #pragma unroll
        for (int q = 0; q < 4; ++q) {
            sc0 += s_U[(q*RPC + w)*F + f0];
            sc1 += s_U[(q*RPC + w)*F + f0 + 1];
        }
        float bvv = sc0; int bf = f0;
        if (sc1 > bvv) { bvv = sc1; bf = f0 + 1; }
        #pragma unroll
        for (int o = 16; o; o >>= 1) {
            float ov = __shfl_xor_sync(0xffffffffu, bvv, o);
            int   of = __shfl_xor_sync(0xffffffffu, bf,  o);
            if (ov > bvv || (ov == bvv && of < bf)) { bvv = ov; bf = of; }
        }
        if (lane < CPB)
            stc_s32(smem_u32(&s_idxt[r*RPC + w]), lane, bf);
    }
    // ---- per-f column-max candidate (warps 8,9), same sum order ----
    else if (w < RPC + 2) {
        const int f = (w - RPC)*32 + lane;
        float best = -INFINITY; int bt = 0;
        #pragma unroll
        for (int t = 0; t < RPC; ++t) {
            float v = 0.f;
            #pragma unroll
            for (int q = 0; q < 4; ++q) v += s_U[(q*RPC + t)*F + f];
            if (v > best) { best = v; bt = t; }
        }
        s_candloc[f] =
            ((unsigned long long)__float_as_uint(best) << 32) | (unsigned)(r*RPC + bt);
    }
    __syncthreads();

    // ---- push candidates: 1 (f, rank) pair per thread (512 pushes) ----
    if (tid < F*CPB)
        stc_u64(smem_u32(&s_cand[r][tid & 63]), tid >> 6, s_candloc[tid & 63]);
    cluster_arrive();
    cluster_wait();   // A: idx_t + candidates visible everywhere

    // ---- wmax/wmin (warp 0) ----
    if (w == 0) {
        float wv[2];
        #pragma unroll
        for (int hh = 0; hh < 2; ++hh) {
            const int f = lane + hh*32;
            unsigned long long c = s_cand[0][f];
            float best = __uint_as_float((unsigned)(c >> 32));
            int   bt   = (int)(c & 0xffffffffu);
            #pragma unroll
            for (int rr = 1; rr < CPB; ++rr) {
                unsigned long long cc = s_cand[rr][f];
                float v = __uint_as_float((unsigned)(cc >> 32));
                if (v > best) { best = v; bt = (int)(cc & 0xffffffffu); }
            }
            wv[hh] = s_ws[bt];
        }
        float mx = fmaxf(wv[0], wv[1]), mn = fminf(wv[0], wv[1]);
        #pragma unroll
        for (int o = 16; o; o >>= 1) {
            mx = fmaxf(mx, __shfl_xor_sync(0xffffffffu, mx, o));
            mn = fminf(mn, __shfl_xor_sync(0xffffffffu, mn, o));
        }
        if (lane == 0) { s_wmm[0] = mx; s_wmm[1] = mn; }
    }
    // ---- amax/amin: warps 16..23, row = w-16 ----
    else if (w >= 16 && w < 16 + RPC) {
        const int t = w - 16;
        float v0 = s_h[t][s_idxt[lane]];
        float v1 = s_h[t][s_idxt[lane + 32]];
        float mx = fmaxf(v0, v1), mn = fminf(v0, v1);
        #pragma unroll
        for (int o = 16; o; o >>= 1) {
            mx = fmaxf(mx, __shfl_xor_sync(0xffffffffu, mx, o));
            mn = fminf(mn, __shfl_xor_sync(0xffffffffu, mn, o));
        }
        if (lane == 0) { s_amax[t] = mx; s_amin[t] = mn; }
    }
    __syncthreads();

    // ---- ms: s_U[0..512) (scp fully consumed) ----
    if (tid < RPC*F) {
        const int t = tid >> 6;
        const float c   = s_o[t][tid & 63];
        const float wmax = s_wmm[0], wmin = s_wmm[1];
        const float amx = s_amax[t], amn = s_amin[t];
        float m = fmaxf(fmaxf(amx*wmax*c, amx*wmin*c),
                        fmaxf(amn*wmax*c, amn*wmin*c));
        s_U[tid] = fast_tanh(m);
    }
    __syncthreads();

    // ---- logit partials: 32 warps, 2 m each ----
    {
        const float4* __restrict__ ms4 = (const float4*)s_U;
        #pragma unroll
        for (int k = 0; k < 2; ++k) {
            const int m = w*2 + k;
            const float4* __restrict__ key4 =
                (const float4*)(mem_keys + m*TF + r*(RPC*F));
            float p0 = 0.f, p1 = 0.f, p2 = 0.f, p3 = 0.f;
            #pragma unroll
            for (int c = 0; c < 4; ++c) {
                float4 kk = key4[c*32 + lane];
                float4 mm = ms4[c*32 + lane];
                p0 = fmaf(kk.x, mm.x, p0);
                p1 = fmaf(kk.y, mm.y, p1);
                p2 = fmaf(kk.z, mm.z, p2);
                p3 = fmaf(kk.w, mm.w, p3);
            }
            float acc = (p0 + p1) + (p2 + p3);
            #pragma unroll
            for (int o = 16; o; o >>= 1)
                acc += __shfl_xor_sync(0xffffffffu, acc, o);
            if (lane < CPB)
                stc_f32(smem_u32(&s_lp[r][m]), lane, acc);
        }
    }
    cluster_arrive();

    // ---- window B: prefetch mem_vals rows this thread needs ----
    float rv[4];
    {
        const int f = tid & 63, q = tid >> 6;
        #pragma unroll
        for (int k = 0; k < 4; ++k)
            rv[k] = __ldg(mem_vals + (q*4 + k)*F + f);
    }
    cluster_wait();   // B: all logit partials visible everywhere

    // ---- softmax / importance (single warp) ----
    if (w == 0) {
        float l0 = 0.f, l1 = 0.f;
        #pragma unroll
        for (int rr = 0; rr < CPB; ++rr) {
            l0 += s_lp[rr][lane];
            l1 += s_lp[rr][lane + 32];
        }
        float mx = fmaxf(l0, l1);
        #pragma unroll
        for (int o = 16; o; o >>= 1)
            mx = fmaxf(mx, __shfl_xor_sync(0xffffffffu, mx, o));
        float e0 = __expf(l0 - mx), e1 = __expf(l1 - mx);
        float s = e0 + e1;
        #pragma unroll
        for (int o = 16; o; o >>= 1)
            s += __shfl_xor_sync(0xffffffffu, s, o);
        float inv = 1.0f / s;
        s_attn[lane]      = e0 * inv;
        s_attn[lane + 32] = e1 * inv;
        if (lane == 0) s_imp = inv;   // max(attn) = exp(0)/sum
    }
    __syncthreads();

    // ---- targets partials: s_U[2048 + q*64 + f], 4 m each ----
    {
        const int f = tid & 63, q = tid >> 6;
        float acc = 0.f;
        #pragma unroll
        for (int k = 0; k < 4; ++k)
            acc = fmaf(s_attn[q*4 + k], rv[k], acc);
        s_U[2048 + q*64 + f] = acc;
    }
    __syncthreads();

    // ---- dist + importances: warps 0..7, row = w ----
    if (w < RPC) {
        float tg0 = 0.f, tg1 = 0.f;
        #pragma unroll
        for (int q = 0; q < 16; ++q) {
            tg0 += s_U[2048 + q*64 + lane];
            tg1 += s_U[2048 + q*64 + lane + 32];
        }
        float d0 = s_in[w][lane]      - tg0;
        float d1 = s_in[w][lane + 32] - tg1;
        float a2 = d0*d0 + d1*d1;
        #pragma unroll
        for (int o = 16; o; o >>= 1)
            a2 += __shfl_xor_sync(0xffffffffu, a2, o);
        if (lane == 0) {
            float nrm = sqrtf(a2);
            float hs  = fminf(fmaxf(0.2f*nrm + 0.5f, 0.f), 1.f);
            d_out[b*T + r*RPC + w]       = 0.5f - hs;
            d_out[B*T + b*T + r*RPC + w] = s_imp;
        }
    }
}

// =====================================================================
extern "C" void kernel_launch(void* const* d_in, const int* in_sizes, int n_in,
                              void* d_out, int out_size) {
    const float* inp      = (const float*)d_in[0];
    const float* Wk       = (const float*)d_in[1];
    const float* bk       = (const float*)d_in[2];
    const float* Wv       = (const float*)d_in[3];
    const float* bv       = (const float*)d_in[4];
    const float* w_s      = (const float*)d_in[5];
    const float* mem_keys = (const float*)d_in[6];
    const float* mem_vals = (const float*)d_in[7];

    fused_all<<<B*CPB, NTH>>>(inp, Wk, bk, Wv, bv, w_s, mem_keys, mem_vals,
                              (float*)d_out);
}